// round 16
// baseline (speedup 1.0000x reference)
#include <cuda_runtime.h>
#include <cuda_bf16.h>
#include <cuda_fp16.h>

#define Bn 2
#define Cn 64
#define CQn 16
#define HWn 9216
#define Dn 96
#define NBLK1 128
#define HWPB1 72      // HWn / NBLK1
#define HWPC 16       // hw columns per CTA in k_out
#define NBLK3 (HWn / HWPC)   // 576

typedef unsigned long long u64;
typedef unsigned int u32;

// Scratch (no runtime allocation allowed)
__device__ float g_partial[Bn * NBLK1 * Dn * Dn];  // per-block energy partials
__device__ float g_attn[Bn * Dn * Dn];             // gamma * softmax(energy), [b][d][e]

// ---- fp16 split helpers ----
__device__ __forceinline__ u32 packhf2(float f0, float f1) {
    u32 r; asm("cvt.rn.f16x2.f32 %0, %1, %2;" : "=r"(r) : "f"(f1), "f"(f0)); return r;
}
__device__ __forceinline__ float hflo(u32 p) {
    return __half2float(__ushort_as_half((unsigned short)(p & 0xffffu)));
}
__device__ __forceinline__ float hfhi(u32 p) {
    return __half2float(__ushort_as_half((unsigned short)(p >> 16)));
}

// ---- ldmatrix / mma wrappers ----
__device__ __forceinline__ void ldsm_x4(u32* r, u32 addr) {
    asm volatile("ldmatrix.sync.aligned.m8n8.x4.shared.b16 {%0,%1,%2,%3}, [%4];"
        : "=r"(r[0]), "=r"(r[1]), "=r"(r[2]), "=r"(r[3]) : "r"(addr));
}
__device__ __forceinline__ void ldsm_x4t(u32* r, u32 addr) {
    asm volatile("ldmatrix.sync.aligned.m8n8.x4.trans.shared.b16 {%0,%1,%2,%3}, [%4];"
        : "=r"(r[0]), "=r"(r[1]), "=r"(r[2]), "=r"(r[3]) : "r"(addr));
}
__device__ __forceinline__ void ldsm_x2(u32* r, u32 addr) {
    asm volatile("ldmatrix.sync.aligned.m8n8.x2.shared.b16 {%0,%1}, [%2];"
        : "=r"(r[0]), "=r"(r[1]) : "r"(addr));
}
__device__ __forceinline__ void ldsm_x2t(u32* r, u32 addr) {
    asm volatile("ldmatrix.sync.aligned.m8n8.x2.trans.shared.b16 {%0,%1}, [%2];"
        : "=r"(r[0]), "=r"(r[1]) : "r"(addr));
}
__device__ __forceinline__ void mma_hf(float* d, const u32* a, const u32* b) {
    asm volatile("mma.sync.aligned.m16n8k16.row.col.f32.f16.f16.f32 "
        "{%0,%1,%2,%3}, {%4,%5,%6,%7}, {%8,%9}, {%0,%1,%2,%3};"
        : "+f"(d[0]), "+f"(d[1]), "+f"(d[2]), "+f"(d[3])
        : "r"(a[0]), "r"(a[1]), "r"(a[2]), "r"(a[3]), "r"(b[0]), "r"(b[1]));
}

// ============================================================================
// Kernel 1: fused q/k projection + energy, split-fp16 MMA (3-MMA, precision-
// critical: logits sigma ~384). Unchanged from the 516.8us passing version.
// ============================================================================

#define E_WQH 0                       // Wq hi [16][72]
#define E_WQL 1152
#define E_WKH 2304
#define E_WKL 3456
#define E_XH  4608                    // X  hi [64 c][104 d]
#define E_XL  11264
#define E_QH  17920                   // q hi [16 o][104 d]
#define E_QL  19584
#define E_KH  21248                   // k hi [16 o][104 e]
#define E_KL  22912
#define E_TOT 24576                   // *2 = 49152 bytes

__global__ void __launch_bounds__(256, 2) k_energy(
    const float* __restrict__ x, const float* __restrict__ Wq,
    const float* __restrict__ bq, const float* __restrict__ Wk,
    const float* __restrict__ bk)
{
    extern __shared__ __align__(16) u32 smw[];
    __half* smh = reinterpret_cast<__half*>(smw);
    const u32 sb = (u32)__cvta_generic_to_shared(smw);

    const int b = blockIdx.y, g = blockIdx.x, t = threadIdx.x;
    const int w = t >> 5, l = t & 31;

    // one-time: split Wq, Wk into hi/lo fp16
    for (int i = t; i < CQn * Cn; i += 256) {
        int o = i >> 6, c = i & 63;
        float vq = Wq[i], vk = Wk[i];
        __half hq = __float2half_rn(vq), hk = __float2half_rn(vk);
        smh[E_WQH + o * 72 + c] = hq;
        smh[E_WQL + o * 72 + c] = __float2half_rn(vq - __half2float(hq));
        smh[E_WKH + o * 72 + c] = hk;
        smh[E_WKL + o * 72 + c] = __float2half_rn(vk - __half2float(hk));
    }

    const int qk  = w >> 2;
    const int nb  = (w & 3) * 3;
    const int gid = l >> 2, tig = l & 3;
    const int waH = qk ? E_WKH : E_WQH;
    const int waL = qk ? E_WKL : E_WQL;
    const int tH  = qk ? E_KH : E_QH;
    const int tL  = qk ? E_KL : E_QL;
    const float* bias = qk ? bk : bq;
    const float bs0 = bias[gid], bs1 = bias[gid + 8];

    // lane-constant ldmatrix address parts
    const int arow  = (l & 7) + (l & 8);          // A non-trans: m-row 0..15
    const int acol8 = ((l >> 4) & 1) * 8;         // A non-trans: k-half
    const int xrow  = (l & 15);                   // B trans: k-row 0..15
    const int pl    = (l >> 4) & 1;               // pair-tile select (x4)
    // A trans (energy): k-row and m-col halves
    const int atrow = (l & 7) + ((l >> 4) & 1) * 8;
    const int amcol = ((l >> 3) & 1) * 8;

    const int mw = w >> 2, nwq = w & 3;

    float E[3][3][4];
    #pragma unroll
    for (int im = 0; im < 3; im++)
        #pragma unroll
        for (int in = 0; in < 3; in++)
            #pragma unroll
            for (int p = 0; p < 4; p++) E[im][in][p] = 0.f;

    const int cp = t >> 2;
    const int d0 = (t & 3) * 24;
    const float* xb = x + (size_t)b * Cn * HWn * Dn;

    // prefetch X column 0
    float4 xf[6];
    {
        const float4* src = reinterpret_cast<const float4*>(
            xb + ((size_t)cp * HWn + (size_t)g * HWPB1) * Dn + d0);
        #pragma unroll
        for (int j = 0; j < 6; j++) xf[j] = src[j];
    }

    __syncthreads();

    for (int it = 0; it < HWPB1; ++it) {
        // ---- stage X: split hi/lo fp16, merged 128-bit stores ----
        #pragma unroll
        for (int jp = 0; jp < 3; jp++) {
            float4 fa = xf[2 * jp], fb = xf[2 * jp + 1];
            int e0 = cp * 104 + d0 + 8 * jp;
            u32 h0 = packhf2(fa.x, fa.y), h1 = packhf2(fa.z, fa.w);
            u32 h2 = packhf2(fb.x, fb.y), h3 = packhf2(fb.z, fb.w);
            u32 l0 = packhf2(fa.x - hflo(h0), fa.y - hfhi(h0));
            u32 l1 = packhf2(fa.z - hflo(h1), fa.w - hfhi(h1));
            u32 l2 = packhf2(fb.x - hflo(h2), fb.y - hfhi(h2));
            u32 l3 = packhf2(fb.z - hflo(h3), fb.w - hfhi(h3));
            *reinterpret_cast<uint4*>(&smh[E_XH + e0]) = make_uint4(h0, h1, h2, h3);
            *reinterpret_cast<uint4*>(&smh[E_XL + e0]) = make_uint4(l0, l1, l2, l3);
        }
        __syncthreads();

        // issue next column's LDGs; consumed next iteration (hides DRAM lat)
        if (it + 1 < HWPB1) {
            const float4* src = reinterpret_cast<const float4*>(
                xb + ((size_t)cp * HWn + (size_t)(g * HWPB1 + it + 1)) * Dn + d0);
            #pragma unroll
            for (int j = 0; j < 6; j++) xf[j] = src[j];
        }

        // ---- projection: acc = W * X + bias (3 n-tiles; B x4-paired) ----
        float acc[3][4];
        #pragma unroll
        for (int nj = 0; nj < 3; nj++) {
            acc[nj][0] = bs0; acc[nj][1] = bs0; acc[nj][2] = bs1; acc[nj][3] = bs1;
        }
        #pragma unroll
        for (int ks = 0; ks < 4; ks++) {
            u32 ah[4], al[4];
            ldsm_x4(ah, sb + 2u * (waH + arow * 72 + acol8 + 16 * ks));
            ldsm_x4(al, sb + 2u * (waL + arow * 72 + acol8 + 16 * ks));
            u32 rh[4], rl[4];
            u32 beP = (16 * ks + xrow) * 104 + 8 * (nb + pl);
            ldsm_x4t(rh, sb + 2u * (E_XH + beP));
            ldsm_x4t(rl, sb + 2u * (E_XL + beP));
            mma_hf(acc[0], ah, rh);     mma_hf(acc[0], ah, rl);     mma_hf(acc[0], al, rh);
            mma_hf(acc[1], ah, rh + 2); mma_hf(acc[1], ah, rl + 2); mma_hf(acc[1], al, rh + 2);
            u32 bh2[2], bl2[2];
            u32 be2 = (16 * ks + xrow) * 104 + 8 * (nb + 2);
            ldsm_x2t(bh2, sb + 2u * (E_XH + be2));
            ldsm_x2t(bl2, sb + 2u * (E_XL + be2));
            mma_hf(acc[2], ah, bh2); mma_hf(acc[2], ah, bl2); mma_hf(acc[2], al, bh2);
        }

        // ---- write q/k NON-transposed [o][104 d], packed 32-bit stores ----
        #pragma unroll
        for (int nj = 0; nj < 3; nj++) {
            int dc = 8 * (nb + nj) + 2 * tig;
            u32 h01 = packhf2(acc[nj][0], acc[nj][1]);
            u32 l01 = packhf2(acc[nj][0] - hflo(h01), acc[nj][1] - hfhi(h01));
            u32 h23 = packhf2(acc[nj][2], acc[nj][3]);
            u32 l23 = packhf2(acc[nj][2] - hflo(h23), acc[nj][3] - hfhi(h23));
            int b0 = gid * 104 + dc;
            int b1 = (gid + 8) * 104 + dc;
            smw[(tH + b0) >> 1] = h01;
            smw[(tL + b0) >> 1] = l01;
            smw[(tH + b1) >> 1] = h23;
            smw[(tL + b1) >> 1] = l23;
        }
        __syncthreads();

        // ---- energy: E += q^T k  (A/B via ldmatrix.trans from [o][*]) ----
        u32 kh[3][2], kl[3][2];
        {
            u32 r4[4];
            u32 beP = xrow * 104 + 8 * (3 * nwq + pl);
            ldsm_x4t(r4, sb + 2u * (E_KH + beP));
            kh[0][0] = r4[0]; kh[0][1] = r4[1]; kh[1][0] = r4[2]; kh[1][1] = r4[3];
            ldsm_x4t(r4, sb + 2u * (E_KL + beP));
            kl[0][0] = r4[0]; kl[0][1] = r4[1]; kl[1][0] = r4[2]; kl[1][1] = r4[3];
            u32 be2 = xrow * 104 + 8 * (3 * nwq + 2);
            ldsm_x2t(kh[2], sb + 2u * (E_KH + be2));
            ldsm_x2t(kl[2], sb + 2u * (E_KL + be2));
        }
        #pragma unroll
        for (int im = 0; im < 3; im++) {
            u32 ah[4], al[4];
            u32 ae = atrow * 104 + 16 * (3 * mw + im) + amcol;
            ldsm_x4t(ah, sb + 2u * (E_QH + ae));
            ldsm_x4t(al, sb + 2u * (E_QL + ae));
            #pragma unroll
            for (int in = 0; in < 3; in++) {
                mma_hf(E[im][in], ah, kh[in]);
                mma_hf(E[im][in], ah, kl[in]);
                mma_hf(E[im][in], al, kh[in]);
            }
        }
        // next X-store touches only XH/XL (disjoint from q/k); the sync after
        // it orders energy reads against the next projection's q/k writes.
    }

    float* dst = g_partial + ((size_t)(b * NBLK1 + g)) * Dn * Dn;
    #pragma unroll
    for (int im = 0; im < 3; im++)
        #pragma unroll
        for (int in = 0; in < 3; in++) {
            int r = 16 * (3 * mw + im) + gid;
            int c = 8 * (3 * nwq + in) + 2 * tig;
            *reinterpret_cast<float2*>(&dst[(size_t)r * Dn + c]) =
                make_float2(E[im][in][0], E[im][in][1]);
            *reinterpret_cast<float2*>(&dst[(size_t)(r + 8) * Dn + c]) =
                make_float2(E[im][in][2], E[im][in][3]);
        }
}

// ============================================================================
// Kernel 2: reduce partials, softmax over e, fold gamma. Stores [b][d][e].
// ============================================================================
__global__ void k_softmax(const float* __restrict__ gamma) {
    const int b = blockIdx.y, d = blockIdx.x;
    const int e = threadIdx.x;
    float v = 0.f;
    for (int g = 0; g < NBLK1; g++)
        v += g_partial[(((size_t)b * NBLK1 + g) * Dn + d) * Dn + e];
    __shared__ float sv[Dn];
    __shared__ float red;
    sv[e] = v;
    __syncthreads();
    if (e == 0) { float m = sv[0]; for (int i = 1; i < Dn; i++) m = fmaxf(m, sv[i]); red = m; }
    __syncthreads();
    float pe = expf(v - red);
    sv[e] = pe;
    __syncthreads();
    if (e == 0) { float s = 0.f; for (int i = 0; i < Dn; i++) s += sv[i]; red = s; }
    __syncthreads();
    g_attn[((size_t)b * Dn + d) * Dn + e] = gamma[0] * pe / red;
}

// ============================================================================
// Kernel 3: fused V projection + attention apply + residual — ALL-SINGLE fp16:
//   GEMM-A: Wv single (hoisted to regs, 0 ldmatrix/iter) x X-hi: 1 MMA/tile
//   GEMM-B: V single x A' single: 1 MMA/tile; V-lo smem removed
//   Residual: X hi+lo reconstruction (exact to 2^-21)
// MMAs 120->60, ldmatrix 50->36 per warp/iter; smem 91.6->69.1 KB.
// Error budget: adds ~2.4e-4 (W) + ~2.4e-4 (V quant) -> rel_err ~1.3-2e-4.
// ============================================================================
#define S_WVH 0                       // Wv single [64][72]
#define S_XH  4608                    // X hi [64][104]
#define S_XL  11264                   // X lo (residual exactness; GEMM uses hi)
#define S_VH  17920                   // V single [64][104]
#define S_AH  24576                   // A' single [96][104]
#define S_TOT 34560                   // *2 = 69120 bytes

__global__ void __launch_bounds__(256, 2) k_out(
    const float* __restrict__ x, const float* __restrict__ Wv,
    const float* __restrict__ bv, float* __restrict__ out)
{
    extern __shared__ __align__(16) u32 smw[];
    __half* smh = reinterpret_cast<__half*>(smw);
    const u32 sb = (u32)__cvta_generic_to_shared(smw);

    const int b = blockIdx.y, g = blockIdx.x, t = threadIdx.x;
    const int w = t >> 5, l = t & 31;

    // one-time: Wv single fp16; A' single fp16
    for (int i = t; i < Cn * Cn; i += 256) {
        int c = i >> 6, cc = i & 63;
        smh[S_WVH + c * 72 + cc] = __float2half_rn(Wv[i]);
    }
    const float* Ab = g_attn + (size_t)b * Dn * Dn;
    for (int i = t; i < Dn * Dn; i += 256) {
        int d = i / 96, e = i % 96;
        smh[S_AH + d * 104 + e] = __float2half_rn(Ab[i]);
    }

    const int mi = w & 3, nj0 = (w >> 2) * 6;
    const int gid = l >> 2, tig = l & 3;
    const float bv0 = bv[16 * mi + gid], bv1 = bv[16 * mi + gid + 8];

    const int arow  = (l & 7) + (l & 8);
    const int acol8 = ((l >> 4) & 1) * 8;
    const int eWa = (16 * mi + arow) * 72 + acol8;
    const int eVa = (16 * mi + arow) * 104 + acol8;
    const int xrow = (l & 15);
    const int pl   = (l >> 4) & 1;
    const int prow = (l & 7);
    const int pcol8 = ((l >> 3) & 1) * 8;

    const int cp = t >> 2;
    const int d0 = (t & 3) * 24;

    const float* xb = x   + (size_t)b * Cn * HWn * Dn;
    float*       ob = out + (size_t)b * Cn * HWn * Dn;

    // prefetch X column 0
    float4 xf[6];
    {
        const float4* src = reinterpret_cast<const float4*>(
            xb + ((size_t)cp * HWn + (size_t)g * HWPC) * Dn + d0);
        #pragma unroll
        for (int j = 0; j < 6; j++) xf[j] = src[j];
    }

    __syncthreads();

    // hoist loop-invariant Wv fragments (16 regs; 0 ldmatrix in loop)
    u32 wfr[4][4];
    #pragma unroll
    for (int ks = 0; ks < 4; ks++)
        ldsm_x4(wfr[ks], sb + 2u * (S_WVH + eWa + 16 * ks));

    for (int it = 0; it < HWPC; ++it) {
        const int hw = g * HWPC + it;

        // ---- stage X: split hi/lo fp16, merged 128-bit stores ----
        #pragma unroll
        for (int jp = 0; jp < 3; jp++) {
            float4 fa = xf[2 * jp], fb = xf[2 * jp + 1];
            int e0 = cp * 104 + d0 + 8 * jp;
            u32 h0 = packhf2(fa.x, fa.y), h1 = packhf2(fa.z, fa.w);
            u32 h2 = packhf2(fb.x, fb.y), h3 = packhf2(fb.z, fb.w);
            u32 l0 = packhf2(fa.x - hflo(h0), fa.y - hfhi(h0));
            u32 l1 = packhf2(fa.z - hflo(h1), fa.w - hfhi(h1));
            u32 l2 = packhf2(fb.x - hflo(h2), fb.y - hfhi(h2));
            u32 l3 = packhf2(fb.z - hflo(h3), fb.w - hfhi(h3));
            *reinterpret_cast<uint4*>(&smh[S_XH + e0]) = make_uint4(h0, h1, h2, h3);
            *reinterpret_cast<uint4*>(&smh[S_XL + e0]) = make_uint4(l0, l1, l2, l3);
        }
        __syncthreads();

        if (it + 1 < HWPC) {
            const float4* src = reinterpret_cast<const float4*>(
                xb + ((size_t)cp * HWn + (size_t)(hw + 1)) * Dn + d0);
            #pragma unroll
            for (int j = 0; j < 6; j++) xf[j] = src[j];
        }

        // ---- GEMM-A: acc = Wv * X-hi + bv (W in regs; 1 MMA per tile) ----
        float acc[6][4];
        #pragma unroll
        for (int nj = 0; nj < 6; nj++) {
            acc[nj][0] = bv0; acc[nj][1] = bv0; acc[nj][2] = bv1; acc[nj][3] = bv1;
        }
        #pragma unroll
        for (int ks = 0; ks < 4; ks++) {
            #pragma unroll
            for (int njp = 0; njp < 6; njp += 2) {
                u32 rh[4];
                u32 beP = (16 * ks + xrow) * 104 + 8 * (nj0 + njp + pl);
                ldsm_x4t(rh, sb + 2u * (S_XH + beP));
                mma_hf(acc[njp],     wfr[ks], rh);
                mma_hf(acc[njp + 1], wfr[ks], rh + 2);
            }
        }

        // ---- V (single fp16) to SMEM ----
        #pragma unroll
        for (int nj = 0; nj < 6; nj++) {
            int e  = 8 * (nj0 + nj) + 2 * tig;
            int r0 = 16 * mi + gid, r1 = r0 + 8;
            smw[(S_VH + r0 * 104 + e) >> 1] = packhf2(acc[nj][0], acc[nj][1]);
            smw[(S_VH + r1 * 104 + e) >> 1] = packhf2(acc[nj][2], acc[nj][3]);
        }
        __syncthreads();

        // ---- GEMM-B: acc = V * A'^T (1 MMA per tile) ----
        #pragma unroll
        for (int nj = 0; nj < 6; nj++) {
            acc[nj][0] = 0.f; acc[nj][1] = 0.f; acc[nj][2] = 0.f; acc[nj][3] = 0.f;
        }
        #pragma unroll
        for (int ks = 0; ks < 6; ks++) {
            u32 vh[4];
            ldsm_x4(vh, sb + 2u * (S_VH + eVa + 16 * ks));
            #pragma unroll
            for (int njp = 0; njp < 6; njp += 2) {
                u32 ra[4];
                u32 beP = (8 * (nj0 + njp + pl) + prow) * 104 + 16 * ks + pcol8;
                ldsm_x4(ra, sb + 2u * (S_AH + beP));
                mma_hf(acc[njp],     vh, ra);
                mma_hf(acc[njp + 1], vh, ra + 2);
            }
        }

        // ---- residual (X = hi + lo, exact) + store ----
        #pragma unroll
        for (int nj = 0; nj < 6; nj++) {
            int d  = 8 * (nj0 + nj) + 2 * tig;
            int r0 = 16 * mi + gid, r1 = r0 + 8;
            u32 xh0 = smw[(S_XH + r0 * 104 + d) >> 1], xl0 = smw[(S_XL + r0 * 104 + d) >> 1];
            u32 xh1 = smw[(S_XH + r1 * 104 + d) >> 1], xl1 = smw[(S_XL + r1 * 104 + d) >> 1];
            float2 o0, o1;
            o0.x = acc[nj][0] + hflo(xh0) + hflo(xl0);
            o0.y = acc[nj][1] + hfhi(xh0) + hfhi(xl0);
            o1.x = acc[nj][2] + hflo(xh1) + hflo(xl1);
            o1.y = acc[nj][3] + hfhi(xh1) + hfhi(xl1);
            *reinterpret_cast<float2*>(ob + ((size_t)r0 * HWn + hw) * Dn + d) = o0;
            *reinterpret_cast<float2*>(ob + ((size_t)r1 * HWn + hw) * Dn + d) = o1;
        }
        __syncthreads();
    }
}

extern "C" void kernel_launch(void* const* d_in, const int* in_sizes, int n_in,
                              void* d_out, int out_size) {
    (void)in_sizes; (void)n_in; (void)out_size;
    const float* x     = (const float*)d_in[0];
    const float* Wq    = (const float*)d_in[1];
    const float* bq    = (const float*)d_in[2];
    const float* Wk    = (const float*)d_in[3];
    const float* bk    = (const float*)d_in[4];
    const float* Wv    = (const float*)d_in[5];
    const float* bv    = (const float*)d_in[6];
    const float* gamma = (const float*)d_in[7];
    float* out = (float*)d_out;

    cudaFuncSetAttribute(k_energy, cudaFuncAttributeMaxDynamicSharedMemorySize, E_TOT * 2);
    cudaFuncSetAttribute(k_out,    cudaFuncAttributeMaxDynamicSharedMemorySize, S_TOT * 2);

    k_energy<<<dim3(NBLK1, Bn), 256, E_TOT * 2>>>(x, Wq, bq, Wk, bk);
    k_softmax<<<dim3(Dn, Bn), Dn>>>(gamma);
    k_out<<<dim3(NBLK3, Bn), 256, S_TOT * 2>>>(x, Wv, bv, out);
}

// round 17
// speedup vs baseline: 1.0698x; 1.0698x over previous
#include <cuda_runtime.h>
#include <cuda_bf16.h>
#include <cuda_fp16.h>

#define Bn 2
#define Cn 64
#define CQn 16
#define HWn 9216
#define Dn 96
#define G1 148        // k_energy CTAs per batch (1 full wave at occ 2)
#define G3 296        // k_out CTAs per batch (2 exact waves at occ 2)

typedef unsigned long long u64;
typedef unsigned int u32;

// Scratch (no runtime allocation allowed)
__device__ float g_partial[Bn * G1 * Dn * Dn];     // per-block energy partials
__device__ float g_attn[Bn * Dn * Dn];             // gamma * softmax(energy), [b][d][e]

// ---- fp16 split helpers ----
__device__ __forceinline__ u32 packhf2(float f0, float f1) {
    u32 r; asm("cvt.rn.f16x2.f32 %0, %1, %2;" : "=r"(r) : "f"(f1), "f"(f0)); return r;
}
__device__ __forceinline__ float hflo(u32 p) {
    return __half2float(__ushort_as_half((unsigned short)(p & 0xffffu)));
}
__device__ __forceinline__ float hfhi(u32 p) {
    return __half2float(__ushort_as_half((unsigned short)(p >> 16)));
}

// ---- ldmatrix / mma wrappers ----
__device__ __forceinline__ void ldsm_x4(u32* r, u32 addr) {
    asm volatile("ldmatrix.sync.aligned.m8n8.x4.shared.b16 {%0,%1,%2,%3}, [%4];"
        : "=r"(r[0]), "=r"(r[1]), "=r"(r[2]), "=r"(r[3]) : "r"(addr));
}
__device__ __forceinline__ void ldsm_x4t(u32* r, u32 addr) {
    asm volatile("ldmatrix.sync.aligned.m8n8.x4.trans.shared.b16 {%0,%1,%2,%3}, [%4];"
        : "=r"(r[0]), "=r"(r[1]), "=r"(r[2]), "=r"(r[3]) : "r"(addr));
}
__device__ __forceinline__ void ldsm_x2(u32* r, u32 addr) {
    asm volatile("ldmatrix.sync.aligned.m8n8.x2.shared.b16 {%0,%1}, [%2];"
        : "=r"(r[0]), "=r"(r[1]) : "r"(addr));
}
__device__ __forceinline__ void ldsm_x2t(u32* r, u32 addr) {
    asm volatile("ldmatrix.sync.aligned.m8n8.x2.trans.shared.b16 {%0,%1}, [%2];"
        : "=r"(r[0]), "=r"(r[1]) : "r"(addr));
}
__device__ __forceinline__ void mma_hf(float* d, const u32* a, const u32* b) {
    asm volatile("mma.sync.aligned.m16n8k16.row.col.f32.f16.f16.f32 "
        "{%0,%1,%2,%3}, {%4,%5,%6,%7}, {%8,%9}, {%0,%1,%2,%3};"
        : "+f"(d[0]), "+f"(d[1]), "+f"(d[2]), "+f"(d[3])
        : "r"(a[0]), "r"(a[1]), "r"(a[2]), "r"(a[3]), "r"(b[0]), "r"(b[1]));
}

// ============================================================================
// Kernel 1: fused q/k projection + energy, split-fp16 MMA (3-MMA, precision-
// critical). Same inner loop as the 516.8us version; grid rebalanced to
// G1=148 CTAs/batch with balanced column ranges (62-63 cols each).
// ============================================================================

#define E_WQH 0                       // Wq hi [16][72]
#define E_WQL 1152
#define E_WKH 2304
#define E_WKL 3456
#define E_XH  4608                    // X  hi [64 c][104 d]
#define E_XL  11264
#define E_QH  17920                   // q hi [16 o][104 d]
#define E_QL  19584
#define E_KH  21248                   // k hi [16 o][104 e]
#define E_KL  22912
#define E_TOT 24576                   // *2 = 49152 bytes

__global__ void __launch_bounds__(256, 2) k_energy(
    const float* __restrict__ x, const float* __restrict__ Wq,
    const float* __restrict__ bq, const float* __restrict__ Wk,
    const float* __restrict__ bk)
{
    extern __shared__ __align__(16) u32 smw[];
    __half* smh = reinterpret_cast<__half*>(smw);
    const u32 sb = (u32)__cvta_generic_to_shared(smw);

    const int b = blockIdx.y, g = blockIdx.x, t = threadIdx.x;
    const int w = t >> 5, l = t & 31;

    // balanced column range for this CTA
    const int hwS = (g * HWn) / G1;
    const int hwE = ((g + 1) * HWn) / G1;

    // one-time: split Wq, Wk into hi/lo fp16
    for (int i = t; i < CQn * Cn; i += 256) {
        int o = i >> 6, c = i & 63;
        float vq = Wq[i], vk = Wk[i];
        __half hq = __float2half_rn(vq), hk = __float2half_rn(vk);
        smh[E_WQH + o * 72 + c] = hq;
        smh[E_WQL + o * 72 + c] = __float2half_rn(vq - __half2float(hq));
        smh[E_WKH + o * 72 + c] = hk;
        smh[E_WKL + o * 72 + c] = __float2half_rn(vk - __half2float(hk));
    }

    const int qk  = w >> 2;
    const int nb  = (w & 3) * 3;
    const int gid = l >> 2, tig = l & 3;
    const int waH = qk ? E_WKH : E_WQH;
    const int waL = qk ? E_WKL : E_WQL;
    const int tH  = qk ? E_KH : E_QH;
    const int tL  = qk ? E_KL : E_QL;
    const float* bias = qk ? bk : bq;
    const float bs0 = bias[gid], bs1 = bias[gid + 8];

    // lane-constant ldmatrix address parts
    const int arow  = (l & 7) + (l & 8);          // A non-trans: m-row 0..15
    const int acol8 = ((l >> 4) & 1) * 8;         // A non-trans: k-half
    const int xrow  = (l & 15);                   // B trans: k-row 0..15
    const int pl    = (l >> 4) & 1;               // pair-tile select (x4)
    const int atrow = (l & 7) + ((l >> 4) & 1) * 8;
    const int amcol = ((l >> 3) & 1) * 8;

    const int mw = w >> 2, nwq = w & 3;

    float E[3][3][4];
    #pragma unroll
    for (int im = 0; im < 3; im++)
        #pragma unroll
        for (int in = 0; in < 3; in++)
            #pragma unroll
            for (int p = 0; p < 4; p++) E[im][in][p] = 0.f;

    const int cp = t >> 2;
    const int d0 = (t & 3) * 24;
    const float* xb = x + (size_t)b * Cn * HWn * Dn;

    // prefetch first column
    float4 xf[6];
    {
        const float4* src = reinterpret_cast<const float4*>(
            xb + ((size_t)cp * HWn + (size_t)hwS) * Dn + d0);
        #pragma unroll
        for (int j = 0; j < 6; j++) xf[j] = src[j];
    }

    __syncthreads();

    for (int hw = hwS; hw < hwE; ++hw) {
        // ---- stage X: split hi/lo fp16, merged 128-bit stores ----
        #pragma unroll
        for (int jp = 0; jp < 3; jp++) {
            float4 fa = xf[2 * jp], fb = xf[2 * jp + 1];
            int e0 = cp * 104 + d0 + 8 * jp;
            u32 h0 = packhf2(fa.x, fa.y), h1 = packhf2(fa.z, fa.w);
            u32 h2 = packhf2(fb.x, fb.y), h3 = packhf2(fb.z, fb.w);
            u32 l0 = packhf2(fa.x - hflo(h0), fa.y - hfhi(h0));
            u32 l1 = packhf2(fa.z - hflo(h1), fa.w - hfhi(h1));
            u32 l2 = packhf2(fb.x - hflo(h2), fb.y - hfhi(h2));
            u32 l3 = packhf2(fb.z - hflo(h3), fb.w - hfhi(h3));
            *reinterpret_cast<uint4*>(&smh[E_XH + e0]) = make_uint4(h0, h1, h2, h3);
            *reinterpret_cast<uint4*>(&smh[E_XL + e0]) = make_uint4(l0, l1, l2, l3);
        }
        __syncthreads();

        // issue next column's LDGs; consumed next iteration (hides DRAM lat)
        if (hw + 1 < hwE) {
            const float4* src = reinterpret_cast<const float4*>(
                xb + ((size_t)cp * HWn + (size_t)(hw + 1)) * Dn + d0);
            #pragma unroll
            for (int j = 0; j < 6; j++) xf[j] = src[j];
        }

        // ---- projection: acc = W * X + bias (3 n-tiles; B x4-paired) ----
        float acc[3][4];
        #pragma unroll
        for (int nj = 0; nj < 3; nj++) {
            acc[nj][0] = bs0; acc[nj][1] = bs0; acc[nj][2] = bs1; acc[nj][3] = bs1;
        }
        #pragma unroll
        for (int ks = 0; ks < 4; ks++) {
            u32 ah[4], al[4];
            ldsm_x4(ah, sb + 2u * (waH + arow * 72 + acol8 + 16 * ks));
            ldsm_x4(al, sb + 2u * (waL + arow * 72 + acol8 + 16 * ks));
            u32 rh[4], rl[4];
            u32 beP = (16 * ks + xrow) * 104 + 8 * (nb + pl);
            ldsm_x4t(rh, sb + 2u * (E_XH + beP));
            ldsm_x4t(rl, sb + 2u * (E_XL + beP));
            mma_hf(acc[0], ah, rh);     mma_hf(acc[0], ah, rl);     mma_hf(acc[0], al, rh);
            mma_hf(acc[1], ah, rh + 2); mma_hf(acc[1], ah, rl + 2); mma_hf(acc[1], al, rh + 2);
            u32 bh2[2], bl2[2];
            u32 be2 = (16 * ks + xrow) * 104 + 8 * (nb + 2);
            ldsm_x2t(bh2, sb + 2u * (E_XH + be2));
            ldsm_x2t(bl2, sb + 2u * (E_XL + be2));
            mma_hf(acc[2], ah, bh2); mma_hf(acc[2], ah, bl2); mma_hf(acc[2], al, bh2);
        }

        // ---- write q/k NON-transposed [o][104 d], packed 32-bit stores ----
        #pragma unroll
        for (int nj = 0; nj < 3; nj++) {
            int dc = 8 * (nb + nj) + 2 * tig;
            u32 h01 = packhf2(acc[nj][0], acc[nj][1]);
            u32 l01 = packhf2(acc[nj][0] - hflo(h01), acc[nj][1] - hfhi(h01));
            u32 h23 = packhf2(acc[nj][2], acc[nj][3]);
            u32 l23 = packhf2(acc[nj][2] - hflo(h23), acc[nj][3] - hfhi(h23));
            int b0 = gid * 104 + dc;
            int b1 = (gid + 8) * 104 + dc;
            smw[(tH + b0) >> 1] = h01;
            smw[(tL + b0) >> 1] = l01;
            smw[(tH + b1) >> 1] = h23;
            smw[(tL + b1) >> 1] = l23;
        }
        __syncthreads();

        // ---- energy: E += q^T k  (A/B via ldmatrix.trans from [o][*]) ----
        u32 kh[3][2], kl[3][2];
        {
            u32 r4[4];
            u32 beP = xrow * 104 + 8 * (3 * nwq + pl);
            ldsm_x4t(r4, sb + 2u * (E_KH + beP));
            kh[0][0] = r4[0]; kh[0][1] = r4[1]; kh[1][0] = r4[2]; kh[1][1] = r4[3];
            ldsm_x4t(r4, sb + 2u * (E_KL + beP));
            kl[0][0] = r4[0]; kl[0][1] = r4[1]; kl[1][0] = r4[2]; kl[1][1] = r4[3];
            u32 be2 = xrow * 104 + 8 * (3 * nwq + 2);
            ldsm_x2t(kh[2], sb + 2u * (E_KH + be2));
            ldsm_x2t(kl[2], sb + 2u * (E_KL + be2));
        }
        #pragma unroll
        for (int im = 0; im < 3; im++) {
            u32 ah[4], al[4];
            u32 ae = atrow * 104 + 16 * (3 * mw + im) + amcol;
            ldsm_x4t(ah, sb + 2u * (E_QH + ae));
            ldsm_x4t(al, sb + 2u * (E_QL + ae));
            #pragma unroll
            for (int in = 0; in < 3; in++) {
                mma_hf(E[im][in], ah, kh[in]);
                mma_hf(E[im][in], ah, kl[in]);
                mma_hf(E[im][in], al, kh[in]);
            }
        }
    }

    float* dst = g_partial + ((size_t)(b * G1 + g)) * Dn * Dn;
    #pragma unroll
    for (int im = 0; im < 3; im++)
        #pragma unroll
        for (int in = 0; in < 3; in++) {
            int r = 16 * (3 * mw + im) + gid;
            int c = 8 * (3 * nwq + in) + 2 * tig;
            *reinterpret_cast<float2*>(&dst[(size_t)r * Dn + c]) =
                make_float2(E[im][in][0], E[im][in][1]);
            *reinterpret_cast<float2*>(&dst[(size_t)(r + 8) * Dn + c]) =
                make_float2(E[im][in][2], E[im][in][3]);
        }
}

// ============================================================================
// Kernel 2: reduce G1 partials, softmax over e, fold gamma. Stores [b][d][e].
// ============================================================================
__global__ void k_softmax(const float* __restrict__ gamma) {
    const int b = blockIdx.y, d = blockIdx.x;
    const int e = threadIdx.x;
    float v = 0.f;
    for (int g = 0; g < G1; g++)
        v += g_partial[(((size_t)b * G1 + g) * Dn + d) * Dn + e];
    __shared__ float sv[Dn];
    __shared__ float red;
    sv[e] = v;
    __syncthreads();
    if (e == 0) { float m = sv[0]; for (int i = 1; i < Dn; i++) m = fmaxf(m, sv[i]); red = m; }
    __syncthreads();
    float pe = expf(v - red);
    sv[e] = pe;
    __syncthreads();
    if (e == 0) { float s = 0.f; for (int i = 0; i < Dn; i++) s += sv[i]; red = s; }
    __syncthreads();
    g_attn[((size_t)b * Dn + d) * Dn + e] = gamma[0] * pe / red;
}

// ============================================================================
// Kernel 3: fused V projection + attention apply + residual — R15 scheme
// (Wv split-fp16 x X-hi: 2 MMAs; V split x A' single: 2 MMAs; exact residual).
// Grid rebalanced to G3=296 CTAs/batch (2 exact waves; prologue halved).
// ============================================================================
#define S_WVH 0                       // Wv hi [64][72]
#define S_WVL 4608
#define S_XH  9216                    // X hi [64][104]
#define S_XL  15872                   // X lo (residual exactness; GEMM uses hi)
#define S_VH  22528                   // V hi [64][104]
#define S_VL  29184
#define S_AH  35840                   // A' single fp16 [96][104]
#define S_TOT 45824                   // *2 = 91648 bytes

__global__ void __launch_bounds__(256, 2) k_out(
    const float* __restrict__ x, const float* __restrict__ Wv,
    const float* __restrict__ bv, float* __restrict__ out)
{
    extern __shared__ __align__(16) u32 smw[];
    __half* smh = reinterpret_cast<__half*>(smw);
    const u32 sb = (u32)__cvta_generic_to_shared(smw);

    const int b = blockIdx.y, g = blockIdx.x, t = threadIdx.x;
    const int w = t >> 5, l = t & 31;

    const int hwS = (g * HWn) / G3;
    const int hwE = ((g + 1) * HWn) / G3;

    // one-time: split Wv (fp16 hi/lo); A' single fp16
    for (int i = t; i < Cn * Cn; i += 256) {
        int c = i >> 6, cc = i & 63;
        float v = Wv[i];
        __half h = __float2half_rn(v);
        smh[S_WVH + c * 72 + cc] = h;
        smh[S_WVL + c * 72 + cc] = __float2half_rn(v - __half2float(h));
    }
    const float* Ab = g_attn + (size_t)b * Dn * Dn;
    for (int i = t; i < Dn * Dn; i += 256) {
        int d = i / 96, e = i % 96;
        smh[S_AH + d * 104 + e] = __float2half_rn(Ab[i]);
    }

    const int mi = w & 3, nj0 = (w >> 2) * 6;
    const int gid = l >> 2, tig = l & 3;
    const float bv0 = bv[16 * mi + gid], bv1 = bv[16 * mi + gid + 8];

    const int arow  = (l & 7) + (l & 8);
    const int acol8 = ((l >> 4) & 1) * 8;
    const int eWa = (16 * mi + arow) * 72 + acol8;
    const int eVa = (16 * mi + arow) * 104 + acol8;
    const int xrow = (l & 15);
    const int pl   = (l >> 4) & 1;
    const int prow = (l & 7);
    const int pcol8 = ((l >> 3) & 1) * 8;

    const int cp = t >> 2;
    const int d0 = (t & 3) * 24;

    const float* xb = x   + (size_t)b * Cn * HWn * Dn;
    float*       ob = out + (size_t)b * Cn * HWn * Dn;

    // prefetch first column
    float4 xf[6];
    {
        const float4* src = reinterpret_cast<const float4*>(
            xb + ((size_t)cp * HWn + (size_t)hwS) * Dn + d0);
        #pragma unroll
        for (int j = 0; j < 6; j++) xf[j] = src[j];
    }

    __syncthreads();

    for (int hw = hwS; hw < hwE; ++hw) {
        // ---- stage X: split hi/lo fp16, merged 128-bit stores ----
        #pragma unroll
        for (int jp = 0; jp < 3; jp++) {
            float4 fa = xf[2 * jp], fb = xf[2 * jp + 1];
            int e0 = cp * 104 + d0 + 8 * jp;
            u32 h0 = packhf2(fa.x, fa.y), h1 = packhf2(fa.z, fa.w);
            u32 h2 = packhf2(fb.x, fb.y), h3 = packhf2(fb.z, fb.w);
            u32 l0 = packhf2(fa.x - hflo(h0), fa.y - hfhi(h0));
            u32 l1 = packhf2(fa.z - hflo(h1), fa.w - hfhi(h1));
            u32 l2 = packhf2(fb.x - hflo(h2), fb.y - hfhi(h2));
            u32 l3 = packhf2(fb.z - hflo(h3), fb.w - hfhi(h3));
            *reinterpret_cast<uint4*>(&smh[S_XH + e0]) = make_uint4(h0, h1, h2, h3);
            *reinterpret_cast<uint4*>(&smh[S_XL + e0]) = make_uint4(l0, l1, l2, l3);
        }
        __syncthreads();

        if (hw + 1 < hwE) {
            const float4* src = reinterpret_cast<const float4*>(
                xb + ((size_t)cp * HWn + (size_t)(hw + 1)) * Dn + d0);
            #pragma unroll
            for (int j = 0; j < 6; j++) xf[j] = src[j];
        }

        // ---- GEMM-A: acc = Wv * X + bv (X-hi only; 2 MMAs per pair) ----
        float acc[6][4];
        #pragma unroll
        for (int nj = 0; nj < 6; nj++) {
            acc[nj][0] = bv0; acc[nj][1] = bv0; acc[nj][2] = bv1; acc[nj][3] = bv1;
        }
        #pragma unroll
        for (int ks = 0; ks < 4; ks++) {
            u32 wh[4], wl[4];
            ldsm_x4(wh, sb + 2u * (S_WVH + eWa + 16 * ks));
            ldsm_x4(wl, sb + 2u * (S_WVL + eWa + 16 * ks));
            #pragma unroll
            for (int njp = 0; njp < 6; njp += 2) {
                u32 rh[4];
                u32 beP = (16 * ks + xrow) * 104 + 8 * (nj0 + njp + pl);
                ldsm_x4t(rh, sb + 2u * (S_XH + beP));
                mma_hf(acc[njp],     wh, rh);     mma_hf(acc[njp],     wl, rh);
                mma_hf(acc[njp + 1], wh, rh + 2); mma_hf(acc[njp + 1], wl, rh + 2);
            }
        }

        // ---- split V (fp16 hi/lo) to SMEM ----
        #pragma unroll
        for (int nj = 0; nj < 6; nj++) {
            int e  = 8 * (nj0 + nj) + 2 * tig;
            int r0 = 16 * mi + gid, r1 = r0 + 8;
            u32 h0 = packhf2(acc[nj][0], acc[nj][1]);
            u32 p0 = packhf2(acc[nj][0] - hflo(h0), acc[nj][1] - hfhi(h0));
            u32 h1 = packhf2(acc[nj][2], acc[nj][3]);
            u32 p1 = packhf2(acc[nj][2] - hflo(h1), acc[nj][3] - hfhi(h1));
            smw[(S_VH + r0 * 104 + e) >> 1] = h0;
            smw[(S_VL + r0 * 104 + e) >> 1] = p0;
            smw[(S_VH + r1 * 104 + e) >> 1] = h1;
            smw[(S_VL + r1 * 104 + e) >> 1] = p1;
        }
        __syncthreads();

        // ---- GEMM-B: acc = V * A'^T (A' single; 2 MMAs per pair) ----
        #pragma unroll
        for (int nj = 0; nj < 6; nj++) {
            acc[nj][0] = 0.f; acc[nj][1] = 0.f; acc[nj][2] = 0.f; acc[nj][3] = 0.f;
        }
        #pragma unroll
        for (int ks = 0; ks < 6; ks++) {
            u32 vh[4], vl[4];
            ldsm_x4(vh, sb + 2u * (S_VH + eVa + 16 * ks));
            ldsm_x4(vl, sb + 2u * (S_VL + eVa + 16 * ks));
            #pragma unroll
            for (int njp = 0; njp < 6; njp += 2) {
                u32 ra[4];
                u32 beP = (8 * (nj0 + njp + pl) + prow) * 104 + 16 * ks + pcol8;
                ldsm_x4(ra, sb + 2u * (S_AH + beP));
                mma_hf(acc[njp],     vh, ra);     mma_hf(acc[njp],     vl, ra);
                mma_hf(acc[njp + 1], vh, ra + 2); mma_hf(acc[njp + 1], vl, ra + 2);
            }
        }

        // ---- residual (X = hi + lo, exact) + store ----
        #pragma unroll
        for (int nj = 0; nj < 6; nj++) {
            int d  = 8 * (nj0 + nj) + 2 * tig;
            int r0 = 16 * mi + gid, r1 = r0 + 8;
            u32 xh0 = smw[(S_XH + r0 * 104 + d) >> 1], xl0 = smw[(S_XL + r0 * 104 + d) >> 1];
            u32 xh1 = smw[(S_XH + r1 * 104 + d) >> 1], xl1 = smw[(S_XL + r1 * 104 + d) >> 1];
            float2 o0, o1;
            o0.x = acc[nj][0] + hflo(xh0) + hflo(xl0);
            o0.y = acc[nj][1] + hfhi(xh0) + hfhi(xl0);
            o1.x = acc[nj][2] + hflo(xh1) + hflo(xl1);
            o1.y = acc[nj][3] + hfhi(xh1) + hfhi(xl1);
            *reinterpret_cast<float2*>(ob + ((size_t)r0 * HWn + hw) * Dn + d) = o0;
            *reinterpret_cast<float2*>(ob + ((size_t)r1 * HWn + hw) * Dn + d) = o1;
        }
        __syncthreads();
    }
}

extern "C" void kernel_launch(void* const* d_in, const int* in_sizes, int n_in,
                              void* d_out, int out_size) {
    (void)in_sizes; (void)n_in; (void)out_size;
    const float* x     = (const float*)d_in[0];
    const float* Wq    = (const float*)d_in[1];
    const float* bq    = (const float*)d_in[2];
    const float* Wk    = (const float*)d_in[3];
    const float* bk    = (const float*)d_in[4];
    const float* Wv    = (const float*)d_in[5];
    const float* bv    = (const float*)d_in[6];
    const float* gamma = (const float*)d_in[7];
    float* out = (float*)d_out;

    cudaFuncSetAttribute(k_energy, cudaFuncAttributeMaxDynamicSharedMemorySize, E_TOT * 2);
    cudaFuncSetAttribute(k_out,    cudaFuncAttributeMaxDynamicSharedMemorySize, S_TOT * 2);

    k_energy<<<dim3(G1, Bn), 256, E_TOT * 2>>>(x, Wq, bq, Wk, bk);
    k_softmax<<<dim3(Dn, Bn), Dn>>>(gamma);
    k_out<<<dim3(G3, Bn), 256, S_TOT * 2>>>(x, Wv, bv, out);
}